// round 9
// baseline (speedup 1.0000x reference)
#include <cuda_runtime.h>
#include <math.h>

constexpr int   NELEM  = 8192;
constexpr int   NB     = 256;            // psi buckets
constexpr int   BCAP   = 96;             // slots/bucket (mean 32, +11 sigma)
constexpr int   PBLK   = 64;             // prep blocks
constexpr int   PTPB   = 128;
constexpr int   NSY    = 4;              // window quarters per bucket
constexpr int   TPB    = 128;
constexpr int   NBLK   = NB * NSY;       // 1024 pairs blocks
constexpr int   WMARG  = 13;             // 13/256 = 0.0508 > 0.05
constexpr int   WBK    = 2 * WMARG + 1;  // 27 window buckets
constexpr int   MAXROW = 7;              // max rows per quarter
constexpr float THRESH = 0.05f;
constexpr float MSEW   = 10.0f;
constexpr float LEPS   = 1e-7f;
constexpr float SENT   = 1.0e9f;

// device scratch; g_bcnt/g_arr self-reset in finalize each replay
__device__ float2   g_bucket[NB][BCAP];
__device__ int      g_bcnt[NB];
__device__ float    g_md[PBLK], g_md2[PBLK], g_mb[PBLK];
__device__ float    g_ps[NBLK];
__device__ int      g_pc[NBLK];
__device__ unsigned g_arr;

// ================= kernel A: pd -> buckets, moments, BCE =================
__global__ void __launch_bounds__(PTPB)
prep(const float* __restrict__ pred, const float* __restrict__ psi) {
    const int tid = threadIdx.x;
    const int i   = blockIdx.x * PTPB + tid;

    float x = __ldg(&pred[i]);
    float y = __ldg(&psi[i]);
    float p = fminf(fmaxf(y, LEPS), 1.0f - LEPS);
    float d = x - __logf(__fdividef(p, 1.0f - p));
    int   b = min(NB - 1, max(0, (int)(y * (float)NB)));

    int pos = atomicAdd(&g_bcnt[b], 1);
    if (pos < BCAP) g_bucket[b][pos] = make_float2(y, d);

    float sd  = d;
    float sd2 = d * d;
    float sb  = fmaxf(x, 0.f) - x * y + __logf(1.0f + __expf(-fabsf(x)));

    #pragma unroll
    for (int o = 16; o > 0; o >>= 1) {
        sd  += __shfl_down_sync(0xffffffffu, sd,  o);
        sd2 += __shfl_down_sync(0xffffffffu, sd2, o);
        sb  += __shfl_down_sync(0xffffffffu, sb,  o);
    }
    __shared__ float rf[3][PTPB / 32];
    if ((tid & 31) == 0) { rf[0][tid >> 5] = sd; rf[1][tid >> 5] = sd2; rf[2][tid >> 5] = sb; }
    __syncthreads();
    if (tid == 0) {
        float a = 0.f, c = 0.f, e = 0.f;
        #pragma unroll
        for (int w = 0; w < PTPB / 32; ++w) { a += rf[0][w]; c += rf[1][w]; e += rf[2][w]; }
        g_md[blockIdx.x] = a; g_md2[blockIdx.x] = c; g_mb[blockIdx.x] = e;
    }
}

// ============ kernel B: invalid-pair window scan + finalize ============
__global__ void __launch_bounds__(TPB)
pairs(const int* __restrict__ flag, float* __restrict__ out) {
    __shared__ float2 win[MAXROW * BCAP];     // compacted window quarter
    __shared__ int    scnt[MAXROW];
    __shared__ int    soff[MAXROW + 1];
    __shared__ float  shs[TPB / 32];
    __shared__ int    shc[TPB / 32];
    __shared__ int    sh_last;

    const int tid  = threadIdx.x;
    const int lane = tid & 31;
    const int wrp  = tid >> 5;
    const int b    = blockIdx.x;
    const int sy   = blockIdx.y;

    // ---- issue i-slot loads first (latency overlaps everything below) ----
    const int cnt_b = min(__ldcg(&g_bcnt[b]), BCAP);
    float2 p0 = __ldcg(&g_bucket[b][lane]);
    float2 p1 = __ldcg(&g_bucket[b][lane + 32]);
    float2 p2 = __ldcg(&g_bucket[b][lane + 64]);
    if (lane      >= cnt_b) p0.x = SENT;
    if (lane + 32 >= cnt_b) p1.x = SENT;
    if (lane + 64 >= cnt_b) p2.x = SENT;

    // ---- my quarter of the 27-bucket window ----
    const int r0 = (WBK * sy)       / NSY;
    const int r1 = (WBK * (sy + 1)) / NSY;
    const int nr = r1 - r0;                        // 6 or 7
    const int babs0 = b - WMARG + r0;

    if (tid < MAXROW) {
        int bb = babs0 + tid;
        scnt[tid] = (tid < nr && bb >= 0 && bb < NB) ? min(__ldcg(&g_bcnt[bb]), BCAP) : 0;
    }
    __syncthreads();
    if (tid == 0) {
        int run = 0;
        #pragma unroll
        for (int r = 0; r < MAXROW; ++r) { soff[r] = run; run += scnt[r]; }
        soff[MAXROW] = run;
    }
    __syncthreads();

    // ---- ragged copy of only-real entries -> contiguous shared ----
    #pragma unroll
    for (int r = 0; r < MAXROW; ++r) {
        const int c = scnt[r];
        if (tid < c) win[soff[r] + tid] = __ldcg(&g_bucket[babs0 + r][tid]);
    }
    __syncthreads();

    const int total = soff[MAXROW];
    const int jw0 = (total * wrp)       >> 2;     // warp's flat j-slice
    const int jw1 = (total * (wrp + 1)) >> 2;

    // ---- flat pair scan; passes 2/3 warp-uniformly skipped if not needed ----
    float sacc = 0.f; int cacc = 0;
    {
        const float y0 = p0.x, d0 = p0.y;
        float s = 0.f; int c = 0;
        #pragma unroll 4
        for (int j = jw0; j < jw1; ++j) {
            float2 pj = win[j];                   // broadcast LDS.64
            float dp = y0 - pj.x;
            float dd = d0 - pj.y;
            if (fabsf(dp) < THRESH) { s = fmaf(dd, dd, s); c++; }
        }
        sacc += s; cacc += c;
    }
    if (cnt_b > 32) {
        const float y1 = p1.x, d1 = p1.y;
        float s = 0.f; int c = 0;
        #pragma unroll 4
        for (int j = jw0; j < jw1; ++j) {
            float2 pj = win[j];
            float dp = y1 - pj.x;
            float dd = d1 - pj.y;
            if (fabsf(dp) < THRESH) { s = fmaf(dd, dd, s); c++; }
        }
        sacc += s; cacc += c;
    }
    if (cnt_b > 64) {
        const float y2 = p2.x, d2 = p2.y;
        float s = 0.f; int c = 0;
        #pragma unroll 4
        for (int j = jw0; j < jw1; ++j) {
            float2 pj = win[j];
            float dp = y2 - pj.x;
            float dd = d2 - pj.y;
            if (fabsf(dp) < THRESH) { s = fmaf(dd, dd, s); c++; }
        }
        sacc += s; cacc += c;
    }

    // ---- block reduction -> slot ----
    #pragma unroll
    for (int o = 16; o > 0; o >>= 1) {
        sacc += __shfl_down_sync(0xffffffffu, sacc, o);
        cacc += __shfl_down_sync(0xffffffffu, cacc, o);
    }
    if (lane == 0) { shs[wrp] = sacc; shc[wrp] = cacc; }
    __syncthreads();
    if (tid == 0) {
        float fs = 0.f; int fc = 0;
        #pragma unroll
        for (int w = 0; w < TPB / 32; ++w) { fs += shs[w]; fc += shc[w]; }
        int slot = sy * NB + b;
        g_ps[slot] = fs; g_pc[slot] = fc;
        __threadfence();
        sh_last = (atomicAdd(&g_arr, 1u) == (unsigned)(NBLK - 1));
        if (sh_last) __threadfence();
    }
    __syncthreads();
    if (!sh_last) return;

    // -------- finalize in last-arriving block --------
    double dsi = 0.0, ds = 0.0, ds2 = 0.0, db = 0.0;
    long long ci = 0;
    for (int k = tid; k < NBLK; k += TPB) {
        dsi += (double)__ldcg(&g_ps[k]);
        ci  += (long long)__ldcg(&g_pc[k]);
    }
    for (int k = tid; k < PBLK; k += TPB) {
        ds  += (double)__ldcg(&g_md[k]);
        ds2 += (double)__ldcg(&g_md2[k]);
        db  += (double)__ldcg(&g_mb[k]);
    }
    #pragma unroll
    for (int o = 16; o > 0; o >>= 1) {
        dsi += __shfl_down_sync(0xffffffffu, dsi, o);
        ci  += __shfl_down_sync(0xffffffffu, ci,  o);
        ds  += __shfl_down_sync(0xffffffffu, ds,  o);
        ds2 += __shfl_down_sync(0xffffffffu, ds2, o);
        db  += __shfl_down_sync(0xffffffffu, db,  o);
    }
    __shared__ double    shd[4][TPB / 32];
    __shared__ long long shl[TPB / 32];
    if (lane == 0) {
        shd[0][wrp] = dsi; shd[1][wrp] = ds; shd[2][wrp] = ds2; shd[3][wrp] = db;
        shl[wrp] = ci;
    }
    __syncthreads();
    if (tid == 0) {
        double Sinv = 0.0, Sd = 0.0, Sd2 = 0.0, Sb = 0.0; long long Cinv = 0;
        #pragma unroll
        for (int w = 0; w < TPB / 32; ++w) {
            Sinv += shd[0][w]; Sd += shd[1][w]; Sd2 += shd[2][w]; Sb += shd[3][w];
            Cinv += shl[w];
        }
        double S_all = 2.0 * (double)NELEM * Sd2 - 2.0 * Sd * Sd;
        long long Cval = (long long)NELEM * (long long)NELEM - Cinv;
        float bce = (float)(Sb / (double)NELEM);
        int bce_only = (flag != nullptr) ? *flag : 0;
        float result;
        if (bce_only) {
            result = bce;
        } else {
            double Sval = S_all - Sinv;
            if (Sval < 0.0) Sval = 0.0;
            double mse = Sval / (double)(Cval > 0 ? Cval : 1);
            result = (Cval > 0) ? (bce + MSEW * (float)mse) : bce;
        }
        out[0] = result;
        g_arr = 0u;
    }
    for (int k = tid; k < NB; k += TPB) g_bcnt[k] = 0;   // reset for next replay
}

extern "C" void kernel_launch(void* const* d_in, const int* in_sizes, int n_in,
                              void* d_out, int out_size) {
    const float* pred = (const float*)d_in[0];
    const float* psi  = (const float*)d_in[1];
    const int*   flag = (n_in >= 3 && in_sizes[2] >= 1) ? (const int*)d_in[2] : nullptr;

    prep<<<PBLK, PTPB>>>(pred, psi);
    pairs<<<dim3(NB, NSY), TPB>>>(flag, (float*)d_out);
}